// round 4
// baseline (speedup 1.0000x reference)
#include <cuda_runtime.h>
#include <cooperative_groups.h>
#include <math.h>

namespace cg = cooperative_groups;

#define ROW_LEN   65536
#define CSIZE     8
#define SEG       (ROW_LEN / CSIZE)     // 8192 elements per CTA
#define THREADS   256
#define VPT       32                    // one tile covers the whole segment
#define HALO      5
#define JOFF      8

#define TREND_SCALING       0.6f
#define DETAIL_PRESERVATION 0.85f
#define SPIKE_THRESHOLD     3.5f
#define SPIKE_DAMPING       0.35f
#define EPS_STD             1e-6f

// XOR swizzle: permutes float4 groups within 128-float blocks; lane stride is
// 32 floats so all float4 LDS/STS are conflict-free.
__device__ __forceinline__ int SX(int j) { return j ^ ((j >> 3) & 0x1C); }

// smem layout (floats)
#define OFF_RED     8224                // 17 floats: warp partials + thr
#define OFF_MAIL    8244                // 16 floats: per-rank (s, ss) mailbox
#define SMEM_FLOATS 8260
#define SMEM_BYTES  (SMEM_FLOATS * 4)

__global__ void __launch_bounds__(THREADS, 2) __cluster_dims__(CSIZE, 1, 1)
fd8_kernel(const float* __restrict__ x, float* __restrict__ out)
{
    extern __shared__ float sm[];
    float* red  = sm + OFF_RED;
    float* mail = sm + OFF_MAIL;

    cg::cluster_group cl = cg::this_cluster();
    const int rank = (int)cl.block_rank();
    const int row  = blockIdx.x / CSIZE;
    const int tid  = threadIdx.x;
    const size_t gbase = (size_t)row * ROW_LEN + (size_t)rank * SEG;
    const int base = tid * VPT;

    // ---- stage segment into swizzled smem (LDG.128 -> STS.128) ----
    {
        const float4* gx = reinterpret_cast<const float4*>(x + gbase);
        #pragma unroll
        for (int g = 0; g < SEG / (THREADS * 4); g++) {     // 8
            int q = g * (THREADS * 4) + tid * 4;
            float4 v = gx[q >> 2];
            *reinterpret_cast<float4*>(sm + SX(JOFF + q)) = v;
        }
    }

    float res[VPT], c[VPT];

    for (int iter = 0; iter < 2; iter++) {
        cl.sync();   // all CTAs' data (stage or iter-1 writes) visible cluster-wide

        // ---- halo fill: 5 left, 5 right, via DSMEM peers / edge reflect ----
        if (tid < HALO) {
            int d = tid + 1;                 // 1..5
            float lv;
            if (rank == 0) {
                lv = sm[SX(JOFF + d)];                       // reflect -d -> d
            } else {
                const float* peer = cl.map_shared_rank(sm, rank - 1);
                lv = peer[SX(JOFF + SEG - d)];
            }
            sm[SX(JOFF - d)] = lv;

            int k = tid;                     // 0..4
            float rv;
            if (rank == CSIZE - 1) {
                rv = sm[SX(JOFF + SEG - 2 - k)];             // reflect L+k -> L-2-k
            } else {
                const float* peer = cl.map_shared_rank(sm, rank + 1);
                rv = peer[SX(JOFF + k)];
            }
            sm[SX(JOFF + SEG + k)] = rv;
        }
        __syncthreads();

        // ---- single fused pass: window -> res[], c[], sum, sumsq ----
        // v[0..48) = elements [base-8, base+40); element (base+o) = v[o+8]
        float v[48];
        #pragma unroll
        for (int i = 0; i < 12; i++) {
            float4 t4 = *reinterpret_cast<const float4*>(
                            sm + SX(JOFF + base - 8 + i * 4));
            v[i * 4 + 0] = t4.x; v[i * 4 + 1] = t4.y;
            v[i * 4 + 2] = t4.z; v[i * 4 + 3] = t4.w;
        }

        float s5  = v[6] + v[7] + v[8] + v[9] + v[10];
        float s11 = v[3] + v[4] + v[5] + v[6] + v[7] + v[8] +
                    v[9] + v[10] + v[11] + v[12] + v[13];
        float s = 0.f, ss = 0.f;
        #pragma unroll
        for (int o = 0; o < VPT; o++) {
            if (o) {
                s5  += v[o + 10] - v[o + 5];
                s11 += v[o + 13] - v[o + 2];
            }
            float r = v[o + 8] - 0.2f * s5;
            res[o] = r;
            s  += r;
            ss += r * r;
            // combined = 0.4*local + 0.6*trend
            c[o] = fmaf(s5, (1.0f - TREND_SCALING) * 0.2f,
                        s11 * (TREND_SCALING / 11.0f));
        }

        // ---- block reduce (deterministic order) ----
        const unsigned m = 0xffffffffu;
        #pragma unroll
        for (int off = 16; off; off >>= 1) {
            s  += __shfl_down_sync(m, s,  off);
            ss += __shfl_down_sync(m, ss, off);
        }
        const int wid = tid >> 5, lid = tid & 31;
        if (lid == 0) { red[wid] = s; red[8 + wid] = ss; }
        __syncthreads();

        // ---- PUSH partials into every CTA's mailbox (incl. own) ----
        if (tid == 0) {
            float bs = 0.f, bss = 0.f;
            #pragma unroll
            for (int w = 0; w < 8; w++) { bs += red[w]; bss += red[8 + w]; }
            #pragma unroll
            for (int r2 = 0; r2 < CSIZE; r2++) {
                float* pm = cl.map_shared_rank(sm, r2) + OFF_MAIL;
                pm[2 * rank]     = bs;
                pm[2 * rank + 1] = bss;
            }
        }
        cl.sync();   // mailbox pushes visible; after this barrier no thread
                     // reads peer SMEM until the next iteration's halo fill

        // ---- LOCAL mailbox reduce, fixed rank order (identical across CTAs) ----
        if (tid == 0) {
            float cs = 0.f, css = 0.f;
            #pragma unroll
            for (int r2 = 0; r2 < CSIZE; r2++) {
                cs  += mail[2 * r2];
                css += mail[2 * r2 + 1];
            }
            const float n = (float)ROW_LEN;
            float var = (css - cs * cs / n) / (n - 1.0f);
            var = fmaxf(var, 0.0f);
            float sc = fmaxf(sqrtf(var), EPS_STD);
            red[16] = sc * SPIKE_THRESHOLD;
        }
        __syncthreads();
        const float thr = red[16];

        // ---- select + store (in-place smem for iter 0, global for iter 1) ----
        if (iter == 0) {
            #pragma unroll
            for (int i = 0; i < VPT / 4; i++) {
                float4 t4;
                float* tp = reinterpret_cast<float*>(&t4);
                #pragma unroll
                for (int q = 0; q < 4; q++) {
                    int o = i * 4 + q;
                    float f = (fabsf(res[o]) > thr)
                                  ? (DETAIL_PRESERVATION * SPIKE_DAMPING)
                                  : DETAIL_PRESERVATION;
                    tp[q] = fmaf(res[o], f, c[o]);
                }
                *reinterpret_cast<float4*>(sm + SX(JOFF + base + i * 4)) = t4;
            }
        } else {
            float4* go = reinterpret_cast<float4*>(out + gbase + base);
            #pragma unroll
            for (int i = 0; i < VPT / 4; i++) {
                float4 t4;
                float* tp = reinterpret_cast<float*>(&t4);
                #pragma unroll
                for (int q = 0; q < 4; q++) {
                    int o = i * 4 + q;
                    float f = (fabsf(res[o]) > thr)
                                  ? (DETAIL_PRESERVATION * SPIKE_DAMPING)
                                  : DETAIL_PRESERVATION;
                    tp[q] = fmaf(res[o], f, c[o]);
                }
                go[i] = t4;
            }
        }
    }

    // No CTA may exit while a peer could still be touching its SMEM
    // (iter-1 halo pulls / mailbox pushes are all pre-barrier, but keep a
    // terminal barrier so lifetime is provably safe).
    cl.sync();
}

extern "C" void kernel_launch(void* const* d_in, const int* in_sizes, int n_in,
                              void* d_out, int out_size)
{
    const float* x = (const float*)d_in[0];
    float* out = (float*)d_out;
    const int rows = in_sizes[0] / ROW_LEN;   // 512

    cudaFuncSetAttribute(fd8_kernel,
                         cudaFuncAttributeMaxDynamicSharedMemorySize, SMEM_BYTES);
    fd8_kernel<<<rows * CSIZE, THREADS, SMEM_BYTES>>>(x, out);
}

// round 5
// speedup vs baseline: 1.1960x; 1.1960x over previous
#include <cuda_runtime.h>
#include <cooperative_groups.h>
#include <math.h>

namespace cg = cooperative_groups;

#define ROW_LEN   65536
#define CSIZE     8
#define SEG       (ROW_LEN / CSIZE)     // 8192 elements per CTA
#define THREADS   256
#define TPT       16                    // elements per thread per tile
#define TILE      (THREADS * TPT)       // 4096
#define NT        (SEG / TILE)          // 2 tiles
#define HALO      5
#define JOFF      8

#define TREND_SCALING       0.6f
#define DETAIL_PRESERVATION 0.85f
#define SPIKE_THRESHOLD     3.5f
#define SPIKE_DAMPING       0.35f
#define EPS_STD             1e-6f

// XOR swizzle: permutes float4 groups within 128-float blocks. With per-thread
// stride of 16 floats, all float4 LDS/STS below are bank-conflict-free.
__device__ __forceinline__ int SX(int j) { return j ^ ((j >> 3) & 0x1C); }

// smem layout (floats)
#define OFF_RED     8224                // 17 floats: warp partials + thr
#define OFF_MAIL    8244                // 16 floats: per-rank (s, ss)
#define SMEM_FLOATS 8260
#define SMEM_BYTES  (SMEM_FLOATS * 4)

__device__ __forceinline__ void ld4(const float* sm, int j, float* dst) {
    float4 t = *reinterpret_cast<const float4*>(sm + SX(j));
    dst[0] = t.x; dst[1] = t.y; dst[2] = t.z; dst[3] = t.w;
}

__global__ void __launch_bounds__(THREADS, 4) __cluster_dims__(CSIZE, 1, 1)
fd5_kernel(const float* __restrict__ x, float* __restrict__ out)
{
    extern __shared__ float sm[];
    float* red  = sm + OFF_RED;
    float* mail = sm + OFF_MAIL;

    cg::cluster_group cl = cg::this_cluster();
    const int rank = (int)cl.block_rank();
    const int row  = blockIdx.x / CSIZE;
    const int tid  = threadIdx.x;
    const size_t gbase = (size_t)row * ROW_LEN + (size_t)rank * SEG;

    // ---- stage segment into swizzled smem (LDG.128 -> STS.128) ----
    {
        const float4* gx = reinterpret_cast<const float4*>(x + gbase);
        #pragma unroll
        for (int g = 0; g < SEG / (THREADS * 4); g++) {     // 8
            int q = g * (THREADS * 4) + tid * 4;
            float4 v = gx[q >> 2];
            *reinterpret_cast<float4*>(sm + SX(JOFF + q)) = v;
        }
    }

    for (int iter = 0; iter < 2; iter++) {
        cl.sync();   // data (stage or iter-0 writes) visible cluster-wide

        // ---- halo fill: 5 left / 5 right via DSMEM peers or edge reflect ----
        if (tid < HALO) {
            int d = tid + 1;                 // 1..5
            float lv;
            if (rank == 0) {
                lv = sm[SX(JOFF + d)];                       // reflect -d -> d
            } else {
                const float* peer = cl.map_shared_rank(sm, rank - 1);
                lv = peer[SX(JOFF + SEG - d)];
            }
            sm[SX(JOFF - d)] = lv;

            int k = tid;                     // 0..4
            float rv;
            if (rank == CSIZE - 1) {
                rv = sm[SX(JOFF + SEG - 2 - k)];             // reflect L+k -> L-2-k
            } else {
                const float* peer = cl.map_shared_rank(sm, rank + 1);
                rv = peer[SX(JOFF + k)];
            }
            sm[SX(JOFF + SEG + k)] = rv;
        }
        __syncthreads();

        // ---- stats pass: sum/sumsq of residual = cur - box5(cur) ----
        float s = 0.f, ss = 0.f;
        #pragma unroll
        for (int t = 0; t < NT; t++) {
            const int tb = t * TILE + tid * TPT;
            float v[24];                      // [tb-4, tb+20)
            #pragma unroll
            for (int i = 0; i < 6; i++) ld4(sm, JOFF + tb - 4 + i * 4, v + i * 4);
            float s5 = v[2] + v[3] + v[4] + v[5] + v[6];
            #pragma unroll
            for (int o = 0; o < TPT; o++) {
                if (o) s5 += v[o + 6] - v[o + 1];
                float r = v[o + 4] - 0.2f * s5;
                s += r;  ss += r * r;
            }
        }

        // ---- block reduce (deterministic) ----
        const unsigned m = 0xffffffffu;
        #pragma unroll
        for (int off = 16; off; off >>= 1) {
            s  += __shfl_down_sync(m, s,  off);
            ss += __shfl_down_sync(m, ss, off);
        }
        const int wid = tid >> 5, lid = tid & 31;
        if (lid == 0) { red[wid] = s; red[8 + wid] = ss; }
        __syncthreads();

        // ---- PUSH partials into every CTA's mailbox (incl. own) ----
        if (tid == 0) {
            float bs = 0.f, bss = 0.f;
            #pragma unroll
            for (int w = 0; w < 8; w++) { bs += red[w]; bss += red[8 + w]; }
            #pragma unroll
            for (int r2 = 0; r2 < CSIZE; r2++) {
                float* pm = cl.map_shared_rank(sm, r2) + OFF_MAIL;
                pm[2 * rank]     = bs;
                pm[2 * rank + 1] = bss;
            }
        }
        cl.sync();   // pushes visible; no peer-SMEM reads after this barrier
                     // until next iteration's halo fill

        // ---- local mailbox reduce, fixed rank order (identical everywhere) ----
        if (tid == 0) {
            float cs = 0.f, css = 0.f;
            #pragma unroll
            for (int r2 = 0; r2 < CSIZE; r2++) {
                cs  += mail[2 * r2];
                css += mail[2 * r2 + 1];
            }
            const float n = (float)ROW_LEN;
            float var = (css - cs * cs / n) / (n - 1.0f);
            var = fmaxf(var, 0.0f);
            float sc = fmaxf(sqrtf(var), EPS_STD);
            red[16] = sc * SPIKE_THRESHOLD;
        }
        __syncthreads();
        const float thr = red[16];

        // ---- update pass: 2 tiles, window [tb-8, tb+24) ----
        // iter 0 writes in-place to smem; tile1's left-dip old values ([4088,4096),
        // read only by tid 0) are stashed before tile0's stores.
        float stash[8];
        if (iter == 0 && tid == 0) {
            ld4(sm, JOFF + TILE - 8, stash);
            ld4(sm, JOFF + TILE - 4, stash + 4);
        }

        #pragma unroll
        for (int t = 0; t < NT; t++) {
            const int tb = t * TILE + tid * TPT;
            float v[32];
            #pragma unroll
            for (int i = 0; i < 8; i++) ld4(sm, JOFF + tb - 8 + i * 4, v + i * 4);
            if (iter == 0 && t == 1 && tid == 0) {
                #pragma unroll
                for (int k = 0; k < 8; k++) v[k] = stash[k];   // old values
            }
            if (iter == 0) __syncthreads();    // all reads done before stores

            float s5  = v[6] + v[7] + v[8] + v[9] + v[10];
            float s11 = v[3] + v[4] + v[5] + v[6] + v[7] + v[8] +
                        v[9] + v[10] + v[11] + v[12] + v[13];
            #pragma unroll
            for (int i = 0; i < TPT / 4; i++) {
                float4 t4;
                float* tp = reinterpret_cast<float*>(&t4);
                #pragma unroll
                for (int q = 0; q < 4; q++) {
                    int o = i * 4 + q;
                    if (o) {
                        s5  += v[o + 10] - v[o + 5];
                        s11 += v[o + 13] - v[o + 2];
                    }
                    float r = v[o + 8] - 0.2f * s5;
                    float f = (fabsf(r) > thr)
                                  ? (DETAIL_PRESERVATION * SPIKE_DAMPING)
                                  : DETAIL_PRESERVATION;
                    float c = fmaf(s5, (1.0f - TREND_SCALING) * 0.2f,
                                   s11 * (TREND_SCALING / 11.0f));
                    tp[q] = fmaf(r, f, c);
                }
                if (iter == 0) {
                    *reinterpret_cast<float4*>(sm + SX(JOFF + tb + i * 4)) = t4;
                } else {
                    *reinterpret_cast<float4*>(out + gbase + tb + i * 4) = t4;
                }
            }
        }
    }

    // lifetime: no CTA exits while a peer may still touch its SMEM
    cl.sync();
}

extern "C" void kernel_launch(void* const* d_in, const int* in_sizes, int n_in,
                              void* d_out, int out_size)
{
    const float* x = (const float*)d_in[0];
    float* out = (float*)d_out;
    const int rows = in_sizes[0] / ROW_LEN;   // 512

    cudaFuncSetAttribute(fd5_kernel,
                         cudaFuncAttributeMaxDynamicSharedMemorySize, SMEM_BYTES);
    fd5_kernel<<<rows * CSIZE, THREADS, SMEM_BYTES>>>(x, out);
}